// round 1
// baseline (speedup 1.0000x reference)
#include <cuda_runtime.h>
#include <math.h>

#define En 2
#define NN 512
#define Bn 64
#define Tt 12
#define Kk 64
#define RN 8   // n-rows per block in the main kernel

// Scratch (static device arrays: allocation-free)
__device__ float g_sup[En * NN * NN];       // supports + adaptive  (2 MB)
__device__ float g_nodes[Bn * Tt * NN];     // normalized nodes, [B][T][N] layout (1.5 MB)

// ---------------------------------------------------------------------------
// Kernel A: sup = supports + u * diag(s * softplus(bias)) * v^T
// Tiled 32x32, 256 threads, 2x2 micro-tile per thread.
// ---------------------------------------------------------------------------
__global__ void sup_kernel(const float* __restrict__ supports,
                           const float* __restrict__ u,
                           const float* __restrict__ s,
                           const float* __restrict__ v,
                           const float* __restrict__ bias) {
    __shared__ float su[32][65];
    __shared__ float sv[32][65];
    __shared__ float ssh[64];

    const int e  = blockIdx.z;
    const int n0 = blockIdx.y * 32;
    const int m0 = blockIdx.x * 32;
    const int tid = threadIdx.y * 16 + threadIdx.x;

    if (tid < 64) {
        float bx = bias[e * Kk + tid];
        float sp = (bx > 20.f) ? bx : log1pf(__expf(bx));   // softplus
        ssh[tid] = s[e * Kk + tid] * sp;
    }
    __syncthreads();

    #pragma unroll
    for (int i = tid; i < 32 * 64; i += 256) {
        int r = i >> 6, k = i & 63;
        su[r][k] = u[(e * NN + n0 + r) * Kk + k] * ssh[k];
        sv[r][k] = v[(e * NN + m0 + r) * Kk + k];
    }
    __syncthreads();

    const int ry = threadIdx.y * 2, rx = threadIdx.x * 2;
    float a00 = 0.f, a01 = 0.f, a10 = 0.f, a11 = 0.f;
    #pragma unroll
    for (int k = 0; k < 64; k++) {
        float u0 = su[ry][k],   u1 = su[ry + 1][k];
        float v0 = sv[rx][k],   v1 = sv[rx + 1][k];
        a00 = fmaf(u0, v0, a00); a01 = fmaf(u0, v1, a01);
        a10 = fmaf(u1, v0, a10); a11 = fmaf(u1, v1, a11);
    }

    const int n = n0 + ry, m = m0 + rx;
    const int base = (e * NN + n) * NN + m;
    g_sup[base]          = supports[base]          + a00;
    g_sup[base + 1]      = supports[base + 1]      + a01;
    g_sup[base + NN]     = supports[base + NN]     + a10;
    g_sup[base + NN + 1] = supports[base + NN + 1] + a11;
}

// ---------------------------------------------------------------------------
// Kernel B: L2-normalize node histories, store transposed [B][T][N]
// inputs: [B, T, N, 2]; take feature 0. One thread per (b, n).
// ---------------------------------------------------------------------------
__global__ void nodes_kernel(const float* __restrict__ inputs) {
    const int idx = blockIdx.x * blockDim.x + threadIdx.x;  // b*512 + n
    const int b = idx >> 9, n = idx & (NN - 1);
    float x[Tt];
    float ss = 0.f;
    #pragma unroll
    for (int t = 0; t < Tt; t++) {
        x[t] = inputs[(((b * Tt + t) * NN) + n) * 2];
        ss = fmaf(x[t], x[t], ss);
    }
    float nrm = sqrtf(ss);
    float inv = 1.0f / fmaxf(nrm, 1e-12f);
    #pragma unroll
    for (int t = 0; t < Tt; t++)
        g_nodes[(b * Tt + t) * NN + n] = x[t] * inv;
}

// ---------------------------------------------------------------------------
// Kernel C: fused main pass.
// Block = (n-tile of RN rows, batch b). 512 threads, one per column m.
// Computes dyn = exp(-||x_n - x_m||), val = relu(sup*(dyn+1)) for both e,
// block-reduces row sums, writes normalized output once.
// ---------------------------------------------------------------------------
__global__ void __launch_bounds__(512, 2)
main_kernel(float* __restrict__ out) {
    __shared__ float xs[Tt * NN];        // nodes[b] staged, [t][n]
    __shared__ float sqs[NN];            // |x_n|^2 per node
    __shared__ float red[2 * RN][17];    // per-warp partial sums (padded)
    __shared__ float inv_s[2 * RN];

    const int b  = blockIdx.y;
    const int n0 = blockIdx.x * RN;
    const int m  = threadIdx.x;
    const int lane = m & 31;
    const int warp = m >> 5;

    // Stage nodes[b] (24 KB), coalesced
    #pragma unroll
    for (int i = m; i < Tt * NN; i += NN)
        xs[i] = g_nodes[b * (Tt * NN) + i];
    __syncthreads();

    // Per-thread column vector + squared norm
    float xm[Tt];
    float sqm = 0.f;
    #pragma unroll
    for (int t = 0; t < Tt; t++) {
        xm[t] = xs[t * NN + m];
        sqm = fmaf(xm[t], xm[t], sqm);
    }
    sqs[m] = sqm;
    __syncthreads();

    float val[RN][2];

    #pragma unroll
    for (int r = 0; r < RN; r++) {
        const int n = n0 + r;
        float inner = 0.f;
        #pragma unroll
        for (int t = 0; t < Tt; t++)
            inner = fmaf(xm[t], xs[t * NN + n], inner);
        float d2 = sqs[n] + sqm - 2.0f * inner;
        float dyn;
        if (d2 > 0.f) {
            float d = d2 * __frsqrt_rn(d2);   // sqrt(d2), fast
            dyn = __expf(-d);
        } else {
            dyn = 1.0f;
        }
        const float f = dyn + 1.0f;
        val[r][0] = fmaxf(g_sup[n * NN + m] * f, 0.f);
        val[r][1] = fmaxf(g_sup[(NN + n) * NN + m] * f, 0.f);
    }

    // Block reduction: 16 row-sums (RN rows x 2 experts)
    #pragma unroll
    for (int r = 0; r < RN; r++) {
        #pragma unroll
        for (int e = 0; e < 2; e++) {
            float v = val[r][e];
            #pragma unroll
            for (int o = 16; o > 0; o >>= 1)
                v += __shfl_down_sync(0xffffffffu, v, o);
            if (lane == 0) red[r * 2 + e][warp] = v;
        }
    }
    __syncthreads();
    if (m < 2 * RN) {
        float ssum = 0.f;
        #pragma unroll
        for (int w = 0; w < 16; w++) ssum += red[m][w];
        inv_s[m] = 1.0f / fmaxf(ssum, 1e-12f);
    }
    __syncthreads();

    // Normalized single write, coalesced over m
    #pragma unroll
    for (int r = 0; r < RN; r++) {
        const int n = n0 + r;
        #pragma unroll
        for (int e = 0; e < 2; e++) {
            out[((e * Bn + b) * NN + n) * NN + m] = val[r][e] * inv_s[r * 2 + e];
        }
    }
}

// ---------------------------------------------------------------------------
extern "C" void kernel_launch(void* const* d_in, const int* in_sizes, int n_in,
                              void* d_out, int out_size) {
    const float* supports = (const float*)d_in[0];  // [2,512,512]
    const float* u        = (const float*)d_in[1];  // [2,512,64]
    const float* s        = (const float*)d_in[2];  // [2,64]
    const float* v        = (const float*)d_in[3];  // [2,512,64]
    const float* bias     = (const float*)d_in[4];  // [2,64]
    const float* inputs   = (const float*)d_in[5];  // [64,12,512,2]
    float* out = (float*)d_out;                     // [2,64,512,512]

    sup_kernel<<<dim3(NN / 32, NN / 32, En), dim3(16, 16)>>>(supports, u, s, v, bias);
    nodes_kernel<<<(Bn * NN) / 512, 512>>>(inputs);
    main_kernel<<<dim3(NN / RN, Bn), NN>>>(out);
}

// round 2
// speedup vs baseline: 1.3123x; 1.3123x over previous
#include <cuda_runtime.h>
#include <math.h>

#define En 2
#define NN 512
#define Bn 64
#define Tt 12
#define Kk 64
#define RN 8     // rows per block tile in main kernel
#define BG 4     // batches per block in main kernel
#define ESTR (Bn * NN * NN)   // e-stride in output

// Scratch (static device arrays: allocation-free)
__device__ __align__(16) float g_sup[En * NN * NN];      // relu(supports + adaptive)  (2 MB)
__device__ __align__(16) float g_nodesT[Bn * NN * Tt];   // normalized nodes, [b][n][t] (1.5 MB)

// ---------------- packed f32x2 + MUFU helpers ----------------
__device__ __forceinline__ unsigned long long pack2(float a, float b) {
    unsigned long long r;
    asm("mov.b64 %0, {%1, %2};" : "=l"(r) : "f"(a), "f"(b));
    return r;
}
__device__ __forceinline__ void unpack2(unsigned long long p, float& a, float& b) {
    asm("mov.b64 {%0, %1}, %2;" : "=f"(a), "=f"(b) : "l"(p));
}
__device__ __forceinline__ unsigned long long fma2_(unsigned long long a, unsigned long long b, unsigned long long c) {
    unsigned long long d;
    asm("fma.rn.f32x2 %0, %1, %2, %3;" : "=l"(d) : "l"(a), "l"(b), "l"(c));
    return d;
}
__device__ __forceinline__ unsigned long long mul2_(unsigned long long a, unsigned long long b) {
    unsigned long long d;
    asm("mul.rn.f32x2 %0, %1, %2;" : "=l"(d) : "l"(a), "l"(b));
    return d;
}
__device__ __forceinline__ unsigned long long add2_(unsigned long long a, unsigned long long b) {
    unsigned long long d;
    asm("add.rn.f32x2 %0, %1, %2;" : "=l"(d) : "l"(a), "l"(b));
    return d;
}
__device__ __forceinline__ float sqrt_ap(float x) { float r; asm("sqrt.approx.f32 %0, %1;" : "=f"(r) : "f"(x)); return r; }
__device__ __forceinline__ float ex2_ap(float x)  { float r; asm("ex2.approx.f32 %0, %1;"  : "=f"(r) : "f"(x)); return r; }
__device__ __forceinline__ float rcp_ap(float x)  { float r; asm("rcp.approx.f32 %0, %1;"  : "=f"(r) : "f"(x)); return r; }

// ---------------------------------------------------------------------------
// Kernel A: g_sup = relu(supports + u * diag(s * softplus(bias)) * v^T)
// 64x64 tile, 256 threads, 4x4 micro-tile, float4 smem.
// ---------------------------------------------------------------------------
__global__ void __launch_bounds__(256) sup_kernel(const float* __restrict__ supports,
                                                  const float* __restrict__ u,
                                                  const float* __restrict__ s,
                                                  const float* __restrict__ v,
                                                  const float* __restrict__ bias) {
    __shared__ float su[64][68];
    __shared__ float sv[64][68];
    __shared__ float ssc[64];

    const int e  = blockIdx.z;
    const int n0 = blockIdx.y * 64;
    const int m0 = blockIdx.x * 64;
    const int tid = threadIdx.x;

    if (tid < 64) {
        float bx = bias[e * Kk + tid];
        float sp = (bx > 20.f) ? bx : log1pf(__expf(bx));   // softplus
        ssc[tid] = s[e * Kk + tid] * sp;
    }
    __syncthreads();

    #pragma unroll
    for (int j = 0; j < 4; j++) {
        int idx = tid + j * 256;       // float4 index over 64x16
        int row = idx >> 4;
        int k   = (idx & 15) << 2;
        float4 uv = *(const float4*)(u + (e * NN + n0 + row) * Kk + k);
        uv.x *= ssc[k]; uv.y *= ssc[k + 1]; uv.z *= ssc[k + 2]; uv.w *= ssc[k + 3];
        *(float4*)&su[row][k] = uv;
        *(float4*)&sv[row][k] = *(const float4*)(v + (e * NN + m0 + row) * Kk + k);
    }
    __syncthreads();

    const int ry = (tid >> 4) << 2;
    const int rx = (tid & 15) << 2;
    float acc[4][4] = {};

    #pragma unroll
    for (int k = 0; k < 64; k += 4) {
        float4 a[4], bq[4];
        #pragma unroll
        for (int i = 0; i < 4; i++) a[i]  = *(const float4*)&su[ry + i][k];
        #pragma unroll
        for (int j = 0; j < 4; j++) bq[j] = *(const float4*)&sv[rx + j][k];
        #pragma unroll
        for (int i = 0; i < 4; i++)
            #pragma unroll
            for (int j = 0; j < 4; j++) {
                float t = fmaf(a[i].x, bq[j].x, acc[i][j]);
                t = fmaf(a[i].y, bq[j].y, t);
                t = fmaf(a[i].z, bq[j].z, t);
                acc[i][j] = fmaf(a[i].w, bq[j].w, t);
            }
    }

    #pragma unroll
    for (int i = 0; i < 4; i++) {
        int base = (e * NN + n0 + ry + i) * NN + m0 + rx;
        float4 sp = *(const float4*)(supports + base);
        float4 o;
        o.x = fmaxf(sp.x + acc[i][0], 0.f);
        o.y = fmaxf(sp.y + acc[i][1], 0.f);
        o.z = fmaxf(sp.z + acc[i][2], 0.f);
        o.w = fmaxf(sp.w + acc[i][3], 0.f);
        *(float4*)(g_sup + base) = o;
    }
}

// ---------------------------------------------------------------------------
// Kernel B: L2-normalize node histories, store [b][n][t] (stride 12).
// ---------------------------------------------------------------------------
__global__ void nodes_kernel(const float* __restrict__ inputs) {
    const int idx = blockIdx.x * blockDim.x + threadIdx.x;  // b*512 + n
    const int b = idx >> 9, n = idx & (NN - 1);
    float x[Tt];
    float ss = 0.f;
    #pragma unroll
    for (int t = 0; t < Tt; t++) {
        x[t] = inputs[(((b * Tt + t) * NN) + n) * 2];
        ss = fmaf(x[t], x[t], ss);
    }
    float inv = 1.0f / fmaxf(sqrtf(ss), 1e-12f);
    float* dst = g_nodesT + (b * NN + n) * Tt;
    float4 o0 = { x[0] * inv, x[1] * inv, x[2]  * inv, x[3]  * inv };
    float4 o1 = { x[4] * inv, x[5] * inv, x[6]  * inv, x[7]  * inv };
    float4 o2 = { x[8] * inv, x[9] * inv, x[10] * inv, x[11] * inv };
    *(float4*)(dst)     = o0;
    *(float4*)(dst + 4) = o1;
    *(float4*)(dst + 8) = o2;
}

// ---------------------------------------------------------------------------
// Kernel C: fused main pass.
// Block: 256 threads, each owns an m-pair (packed f32x2), RN rows x BG batches.
// dyn = exp(-sqrt(2 - 2*<x_n,x_m>)); val = (dyn+1)*rsup; per-row L1 normalize.
// ---------------------------------------------------------------------------
__global__ void __launch_bounds__(256, 3)
main_kernel(float* __restrict__ out) {
    __shared__ float xs[NN * Tt];                           // [n][t], 24 KB
    __shared__ __align__(16) unsigned long long xd[RN * Tt]; // packed {xn,xn} per tile row
    __shared__ float vsm[2][RN][NN];                        // 32 KB
    __shared__ float invs[RN * 2];

    const int tid  = threadIdx.x;
    const int lane = tid & 31;
    const int warp = tid >> 5;
    const int n0 = blockIdx.x * RN;
    const int b0 = blockIdx.y * BG;
    const int m0 = tid * 2;

    const unsigned long long CM2 = 0xC0000000C0000000ULL;  // {-2,-2}
    const unsigned long long CP2 = 0x4000000040000000ULL;  // {+2,+2}

    for (int bi = 0; bi < BG; ++bi) {
        const int b = b0 + bi;
        __syncthreads();   // protect smem reuse across batches

        // Stage nodes[b] (6144 floats = 1536 float4)
        {
            const float4* src = (const float4*)(g_nodesT + b * (NN * Tt));
            float4* dst = (float4*)xs;
            #pragma unroll
            for (int i = 0; i < 6; i++) dst[tid + i * 256] = src[tid + i * 256];
        }
        // Build duplicated-row table xd (from global, independent of xs)
        if (tid < RN * Tt) {
            int r = tid / Tt, t = tid - r * Tt;
            float xv = g_nodesT[b * (NN * Tt) + (n0 + r) * Tt + t];
            xd[tid] = pack2(xv, xv);
        }
        __syncthreads();

        // xm pair packed: rows m0 and m0+1 are contiguous 12-float runs
        unsigned long long xm2[Tt];
        {
            const float4* xa = (const float4*)(xs + m0 * Tt);
            float4 a0 = xa[0], a1 = xa[1], a2 = xa[2];
            float4 c0 = xa[3], c1 = xa[4], c2 = xa[5];
            xm2[0]  = pack2(a0.x, c0.x); xm2[1]  = pack2(a0.y, c0.y);
            xm2[2]  = pack2(a0.z, c0.z); xm2[3]  = pack2(a0.w, c0.w);
            xm2[4]  = pack2(a1.x, c1.x); xm2[5]  = pack2(a1.y, c1.y);
            xm2[6]  = pack2(a1.z, c1.z); xm2[7]  = pack2(a1.w, c1.w);
            xm2[8]  = pack2(a2.x, c2.x); xm2[9]  = pack2(a2.y, c2.y);
            xm2[10] = pack2(a2.z, c2.z); xm2[11] = pack2(a2.w, c2.w);
        }

        #pragma unroll
        for (int r = 0; r < RN; r++) {
            const ulonglong2* xdp = (const ulonglong2*)&xd[r * Tt];
            ulonglong2 q0 = xdp[0], q1 = xdp[1], q2 = xdp[2];
            ulonglong2 q3 = xdp[3], q4 = xdp[4], q5 = xdp[5];
            unsigned long long pa = mul2_(xm2[0], q0.x);
            unsigned long long pb = mul2_(xm2[1], q0.y);
            pa = fma2_(xm2[2],  q1.x, pa);  pb = fma2_(xm2[3],  q1.y, pb);
            pa = fma2_(xm2[4],  q2.x, pa);  pb = fma2_(xm2[5],  q2.y, pb);
            pa = fma2_(xm2[6],  q3.x, pa);  pb = fma2_(xm2[7],  q3.y, pb);
            pa = fma2_(xm2[8],  q4.x, pa);  pb = fma2_(xm2[9],  q4.y, pb);
            pa = fma2_(xm2[10], q5.x, pa);  pb = fma2_(xm2[11], q5.y, pb);
            unsigned long long inner2 = add2_(pa, pb);
            unsigned long long d2p = fma2_(inner2, CM2, CP2);   // 2 - 2*inner
            float d20, d21;
            unpack2(d2p, d20, d21);
            d20 = fmaxf(d20, 0.f);
            d21 = fmaxf(d21, 0.f);
            float dd0 = sqrt_ap(d20), dd1 = sqrt_ap(d21);
            float f0 = ex2_ap(-1.4426950408889634f * dd0) + 1.0f;
            float f1 = ex2_ap(-1.4426950408889634f * dd1) + 1.0f;

            const int n = n0 + r;
            float2 s0 = *(const float2*)&g_sup[n * NN + m0];
            float2 s1 = *(const float2*)&g_sup[NN * NN + n * NN + m0];
            float2 v0 = make_float2(f0 * s0.x, f1 * s0.y);
            float2 v1 = make_float2(f0 * s1.x, f1 * s1.y);
            *(float2*)&vsm[0][r][m0] = v0;
            *(float2*)&vsm[1][r][m0] = v1;
        }
        __syncthreads();

        // One warp per row: strided read + butterfly
        {
            const int r = warp;   // 8 warps == RN rows
            const float2* p0 = (const float2*)vsm[0][r];
            const float2* p1 = (const float2*)vsm[1][r];
            float sum0 = 0.f, sum1 = 0.f;
            #pragma unroll
            for (int i = 0; i < 8; i++) { float2 vv = p0[lane + 32 * i]; sum0 += vv.x + vv.y; }
            #pragma unroll
            for (int i = 0; i < 8; i++) { float2 vv = p1[lane + 32 * i]; sum1 += vv.x + vv.y; }
            #pragma unroll
            for (int o = 16; o > 0; o >>= 1) {
                sum0 += __shfl_xor_sync(0xffffffffu, sum0, o);
                sum1 += __shfl_xor_sync(0xffffffffu, sum1, o);
            }
            if (lane == 0) {
                invs[r * 2]     = rcp_ap(fmaxf(sum0, 1e-12f));
                invs[r * 2 + 1] = rcp_ap(fmaxf(sum1, 1e-12f));
            }
        }
        __syncthreads();

        // Scaled write-out (coalesced float2)
        float* ob = out + (b * NN + n0) * NN + m0;
        #pragma unroll
        for (int r = 0; r < RN; r++) {
            float iv0 = invs[r * 2], iv1 = invs[r * 2 + 1];
            float2 v0 = *(const float2*)&vsm[0][r][m0];
            float2 v1 = *(const float2*)&vsm[1][r][m0];
            *(float2*)(ob + r * NN)         = make_float2(v0.x * iv0, v0.y * iv0);
            *(float2*)(ob + ESTR + r * NN)  = make_float2(v1.x * iv1, v1.y * iv1);
        }
    }
}

// ---------------------------------------------------------------------------
extern "C" void kernel_launch(void* const* d_in, const int* in_sizes, int n_in,
                              void* d_out, int out_size) {
    const float* supports = (const float*)d_in[0];  // [2,512,512]
    const float* u        = (const float*)d_in[1];  // [2,512,64]
    const float* s        = (const float*)d_in[2];  // [2,64]
    const float* v        = (const float*)d_in[3];  // [2,512,64]
    const float* bias     = (const float*)d_in[4];  // [2,64]
    const float* inputs   = (const float*)d_in[5];  // [64,12,512,2]
    float* out = (float*)d_out;                     // [2,64,512,512]

    sup_kernel<<<dim3(NN / 64, NN / 64, En), 256>>>(supports, u, s, v, bias);
    nodes_kernel<<<(Bn * NN) / 256, 256>>>(inputs);
    main_kernel<<<dim3(NN / RN, Bn / BG), 256>>>(out);
}

// round 3
// speedup vs baseline: 1.5044x; 1.1463x over previous
#include <cuda_runtime.h>
#include <math.h>

#define En 2
#define NN 512
#define Bn 64
#define Tt 12
#define Kk 64
#define RN 8     // rows per block tile in main kernel
#define BG 4     // batches per block in main kernel
#define ESTR (Bn * NN * NN)   // e-stride in output

// Dynamic smem layout for main kernel
#define OFF_SUP  0              // float [2][RN][512]  = 32768 B
#define OFF_VSM  32768          // float [2][RN][512]  = 32768 B
#define OFF_XD   65536          // ull   [RN*12]       = 768 B
#define OFF_INV  66304          // float [16]
#define SMEM_MAIN 66560

// Scratch (static device arrays: allocation-free)
__device__ __align__(16) float g_sup[En * NN * NN];      // relu(supports + adaptive)  (2 MB)
__device__ __align__(16) float g_nodesT[Bn * NN * Tt];   // normalized nodes, [b][n][t] (1.5 MB)

// ---------------- packed f32x2 + MUFU helpers ----------------
__device__ __forceinline__ unsigned long long pack2(float a, float b) {
    unsigned long long r;
    asm("mov.b64 %0, {%1, %2};" : "=l"(r) : "f"(a), "f"(b));
    return r;
}
__device__ __forceinline__ void unpack2(unsigned long long p, float& a, float& b) {
    asm("mov.b64 {%0, %1}, %2;" : "=f"(a), "=f"(b) : "l"(p));
}
__device__ __forceinline__ unsigned long long fma2_(unsigned long long a, unsigned long long b, unsigned long long c) {
    unsigned long long d;
    asm("fma.rn.f32x2 %0, %1, %2, %3;" : "=l"(d) : "l"(a), "l"(b), "l"(c));
    return d;
}
__device__ __forceinline__ unsigned long long mul2_(unsigned long long a, unsigned long long b) {
    unsigned long long d;
    asm("mul.rn.f32x2 %0, %1, %2;" : "=l"(d) : "l"(a), "l"(b));
    return d;
}
__device__ __forceinline__ unsigned long long add2_(unsigned long long a, unsigned long long b) {
    unsigned long long d;
    asm("add.rn.f32x2 %0, %1, %2;" : "=l"(d) : "l"(a), "l"(b));
    return d;
}
__device__ __forceinline__ float sqrt_ap(float x) { float r; asm("sqrt.approx.f32 %0, %1;" : "=f"(r) : "f"(x)); return r; }
__device__ __forceinline__ float ex2_neg(float x) { float r; asm("ex2.approx.f32 %0, %1;"  : "=f"(r) : "f"(-x)); return r; }
__device__ __forceinline__ float rcp_ap(float x)  { float r; asm("rcp.approx.f32 %0, %1;"  : "=f"(r) : "f"(x)); return r; }

// ---------------------------------------------------------------------------
// Kernel A (fused prep):
//   z = 0,1 : g_sup[e] = relu(supports + u * diag(s*softplus(bias)) * v^T)
//             64x64 tile, 256 threads, 4x4 micro-tile, TRANSPOSED [k][row] smem
//   z = 2   : L2-normalize node histories -> g_nodesT [b][n][t]
// ---------------------------------------------------------------------------
__global__ void __launch_bounds__(256) prep_kernel(const float* __restrict__ supports,
                                                   const float* __restrict__ u,
                                                   const float* __restrict__ s,
                                                   const float* __restrict__ v,
                                                   const float* __restrict__ bias,
                                                   const float* __restrict__ inputs) {
    const int tid = threadIdx.x;

    if (blockIdx.z == 2) {
        // ---- nodes path: 64 blocks x 256 threads, 2 items each ----
        const int g = (blockIdx.y * 8 + blockIdx.x) * 256 + tid;
        #pragma unroll
        for (int it = 0; it < 2; it++) {
            const int i = g + it * 16384;      // b*512 + n
            const int b = i >> 9, n = i & (NN - 1);
            float x[Tt];
            float ss = 0.f;
            #pragma unroll
            for (int t = 0; t < Tt; t++) {
                x[t] = inputs[(((b * Tt + t) * NN) + n) * 2];
                ss = fmaf(x[t], x[t], ss);
            }
            float inv = 1.0f / fmaxf(sqrtf(ss), 1e-12f);
            float* dst = g_nodesT + (b * NN + n) * Tt;
            float4 o0 = { x[0] * inv, x[1] * inv, x[2]  * inv, x[3]  * inv };
            float4 o1 = { x[4] * inv, x[5] * inv, x[6]  * inv, x[7]  * inv };
            float4 o2 = { x[8] * inv, x[9] * inv, x[10] * inv, x[11] * inv };
            *(float4*)(dst)     = o0;
            *(float4*)(dst + 4) = o1;
            *(float4*)(dst + 8) = o2;
        }
        return;
    }

    // ---- sup path ----
    __shared__ float su_t[Kk][68];   // [k][n], scaled by s*softplus(bias)
    __shared__ float sv_t[Kk][68];   // [k][m]
    __shared__ float ssc[Kk];

    const int e  = blockIdx.z;
    const int n0 = blockIdx.y * 64;
    const int m0 = blockIdx.x * 64;

    if (tid < 64) {
        float bx = bias[e * Kk + tid];
        float sp = (bx > 20.f) ? bx : log1pf(__expf(bx));   // softplus
        ssc[tid] = s[e * Kk + tid] * sp;
    }
    __syncthreads();

    // Load u,v transposed into smem. row = idx & 63 (lanes -> consecutive rows:
    // conflict-free STS), kq = idx >> 6.
    #pragma unroll
    for (int j = 0; j < 4; j++) {
        int idx = tid + j * 256;
        int row = idx & 63;
        int kq  = idx >> 6;        // 0..15
        float4 uv = *(const float4*)(u + (e * NN + n0 + row) * Kk + kq * 4);
        float4 vv = *(const float4*)(v + (e * NN + m0 + row) * Kk + kq * 4);
        su_t[kq * 4 + 0][row] = uv.x * ssc[kq * 4 + 0];
        su_t[kq * 4 + 1][row] = uv.y * ssc[kq * 4 + 1];
        su_t[kq * 4 + 2][row] = uv.z * ssc[kq * 4 + 2];
        su_t[kq * 4 + 3][row] = uv.w * ssc[kq * 4 + 3];
        sv_t[kq * 4 + 0][row] = vv.x;
        sv_t[kq * 4 + 1][row] = vv.y;
        sv_t[kq * 4 + 2][row] = vv.z;
        sv_t[kq * 4 + 3][row] = vv.w;
    }
    __syncthreads();

    const int ry = (tid >> 4) << 2;
    const int rx = (tid & 15) << 2;
    float acc[4][4] = {};

    #pragma unroll
    for (int k = 0; k < 64; k++) {
        float4 a  = *(const float4*)&su_t[k][ry];   // 4 n-values (broadcast-ish)
        float4 bq = *(const float4*)&sv_t[k][rx];   // 4 m-values (contiguous)
        acc[0][0] = fmaf(a.x, bq.x, acc[0][0]); acc[0][1] = fmaf(a.x, bq.y, acc[0][1]);
        acc[0][2] = fmaf(a.x, bq.z, acc[0][2]); acc[0][3] = fmaf(a.x, bq.w, acc[0][3]);
        acc[1][0] = fmaf(a.y, bq.x, acc[1][0]); acc[1][1] = fmaf(a.y, bq.y, acc[1][1]);
        acc[1][2] = fmaf(a.y, bq.z, acc[1][2]); acc[1][3] = fmaf(a.y, bq.w, acc[1][3]);
        acc[2][0] = fmaf(a.z, bq.x, acc[2][0]); acc[2][1] = fmaf(a.z, bq.y, acc[2][1]);
        acc[2][2] = fmaf(a.z, bq.z, acc[2][2]); acc[2][3] = fmaf(a.z, bq.w, acc[2][3]);
        acc[3][0] = fmaf(a.w, bq.x, acc[3][0]); acc[3][1] = fmaf(a.w, bq.y, acc[3][1]);
        acc[3][2] = fmaf(a.w, bq.z, acc[3][2]); acc[3][3] = fmaf(a.w, bq.w, acc[3][3]);
    }

    #pragma unroll
    for (int i = 0; i < 4; i++) {
        int base = (e * NN + n0 + ry + i) * NN + m0 + rx;
        float4 sp = *(const float4*)(supports + base);
        float4 o;
        o.x = fmaxf(sp.x + acc[i][0], 0.f);
        o.y = fmaxf(sp.y + acc[i][1], 0.f);
        o.z = fmaxf(sp.z + acc[i][2], 0.f);
        o.w = fmaxf(sp.w + acc[i][3], 0.f);
        *(float4*)(g_sup + base) = o;
    }
}

// ---------------------------------------------------------------------------
// Kernel C: fused main pass.
// Block: 256 threads, each owns an m-pair (packed f32x2), RN rows x BG batches.
// sup tile cached in smem for the whole batch group (L2 traffic /BG).
// f = 1 + exp(-sqrt(2-2<x_n,x_m>)); val = f*rsup; per-row L1 normalize.
// ---------------------------------------------------------------------------
__global__ void __launch_bounds__(256, 3)
main_kernel(float* __restrict__ out) {
    extern __shared__ char dynsm[];
    float* sup_s = (float*)(dynsm + OFF_SUP);                 // [e*8+r][512]
    float* vsm   = (float*)(dynsm + OFF_VSM);                 // [e*8+r][512]
    unsigned long long* xd = (unsigned long long*)(dynsm + OFF_XD);
    float* invs  = (float*)(dynsm + OFF_INV);

    const int tid  = threadIdx.x;
    const int lane = tid & 31;
    const int warp = tid >> 5;
    const int n0 = blockIdx.x * RN;
    const int b0 = blockIdx.y * BG;
    const int m0 = tid * 2;

    // Stage sup tile (both e): 2048 float4
    #pragma unroll
    for (int i = 0; i < 8; i++) {
        int idx = i * 256 + tid;                    // e*1024 + r*128 + q
        int e = idx >> 10, r = (idx >> 7) & 7, q = idx & 127;
        ((float4*)sup_s)[idx] =
            *(const float4*)(g_sup + e * (NN * NN) + (n0 + r) * NN + q * 4);
    }

    // 2 * (ln2^-1)^2
    const float C = 4.1627379620112154f;
    const unsigned long long CM = pack2(-C, -C);
    const unsigned long long CP = pack2( C,  C);

    for (int bi = 0; bi < BG; ++bi) {
        const int b = b0 + bi;
        if (bi) __syncthreads();   // prev writeout done before vsm/xd reuse

        // duplicated row-node table (96 floats from gmem)
        if (tid < RN * Tt) {
            int r = tid / Tt, t = tid - r * Tt;
            float xv = g_nodesT[b * (NN * Tt) + (n0 + r) * Tt + t];
            xd[tid] = pack2(xv, xv);
        }

        // xm pair packed, straight from gmem (coalesced, L2-resident)
        unsigned long long xm2[Tt];
        {
            const float4* xa = (const float4*)(g_nodesT + b * (NN * Tt)) + tid * 6;
            float4 a0 = xa[0], a1 = xa[1], a2 = xa[2];
            float4 c0 = xa[3], c1 = xa[4], c2 = xa[5];
            xm2[0]  = pack2(a0.x, c0.x); xm2[1]  = pack2(a0.y, c0.y);
            xm2[2]  = pack2(a0.z, c0.z); xm2[3]  = pack2(a0.w, c0.w);
            xm2[4]  = pack2(a1.x, c1.x); xm2[5]  = pack2(a1.y, c1.y);
            xm2[6]  = pack2(a1.z, c1.z); xm2[7]  = pack2(a1.w, c1.w);
            xm2[8]  = pack2(a2.x, c2.x); xm2[9]  = pack2(a2.y, c2.y);
            xm2[10] = pack2(a2.z, c2.z); xm2[11] = pack2(a2.w, c2.w);
        }
        __syncthreads();   // xd ready (and, on bi==0, sup_s ready)

        #pragma unroll
        for (int r = 0; r < RN; r++) {
            const ulonglong2* xdp = (const ulonglong2*)&xd[r * Tt];
            ulonglong2 q0 = xdp[0], q1 = xdp[1], q2 = xdp[2];
            ulonglong2 q3 = xdp[3], q4 = xdp[4], q5 = xdp[5];
            unsigned long long pa = mul2_(xm2[0], q0.x);
            unsigned long long pb = mul2_(xm2[1], q0.y);
            pa = fma2_(xm2[2],  q1.x, pa);  pb = fma2_(xm2[3],  q1.y, pb);
            pa = fma2_(xm2[4],  q2.x, pa);  pb = fma2_(xm2[5],  q2.y, pb);
            pa = fma2_(xm2[6],  q3.x, pa);  pb = fma2_(xm2[7],  q3.y, pb);
            pa = fma2_(xm2[8],  q4.x, pa);  pb = fma2_(xm2[9],  q4.y, pb);
            pa = fma2_(xm2[10], q5.x, pa);  pb = fma2_(xm2[11], q5.y, pb);
            unsigned long long inner2 = add2_(pa, pb);
            unsigned long long d2p = fma2_(inner2, CM, CP);  // C*(2-2i)/2 -> (1.4427*d)^2
            float d20, d21;
            unpack2(d2p, d20, d21);
            d20 = fmaxf(d20, 0.f);
            d21 = fmaxf(d21, 0.f);
            float f0 = ex2_neg(sqrt_ap(d20)) + 1.0f;
            float f1 = ex2_neg(sqrt_ap(d21)) + 1.0f;

            float2 s0 = *(const float2*)&sup_s[r * NN + m0];
            float2 s1 = *(const float2*)&sup_s[(RN + r) * NN + m0];
            *(float2*)&vsm[r * NN + m0]        = make_float2(f0 * s0.x, f1 * s0.y);
            *(float2*)&vsm[(RN + r) * NN + m0] = make_float2(f0 * s1.x, f1 * s1.y);
        }
        __syncthreads();

        // One warp per row: strided float4 reads + butterfly
        {
            const int r = warp;
            float sum0 = 0.f, sum1 = 0.f;
            const float4* p0 = (const float4*)&vsm[r * NN];
            const float4* p1 = (const float4*)&vsm[(RN + r) * NN];
            #pragma unroll
            for (int i = 0; i < 4; i++) {
                float4 v0 = p0[lane + 32 * i];
                float4 v1 = p1[lane + 32 * i];
                sum0 += (v0.x + v0.y) + (v0.z + v0.w);
                sum1 += (v1.x + v1.y) + (v1.z + v1.w);
            }
            #pragma unroll
            for (int o = 16; o > 0; o >>= 1) {
                sum0 += __shfl_xor_sync(0xffffffffu, sum0, o);
                sum1 += __shfl_xor_sync(0xffffffffu, sum1, o);
            }
            if (lane == 0) {
                invs[r * 2]     = rcp_ap(fmaxf(sum0, 1e-12f));
                invs[r * 2 + 1] = rcp_ap(fmaxf(sum1, 1e-12f));
            }
        }
        __syncthreads();

        // Scaled write-out, float4 coalesced
        #pragma unroll
        for (int i = 0; i < 8; i++) {
            int idx = i * 256 + tid;              // e*1024 + r*128 + q
            int e = idx >> 10, r = (idx >> 7) & 7, q = idx & 127;
            float iv = invs[r * 2 + e];
            float4 vv = ((const float4*)vsm)[idx];
            vv.x *= iv; vv.y *= iv; vv.z *= iv; vv.w *= iv;
            *(float4*)(out + e * ESTR + (b * NN + n0 + r) * NN + q * 4) = vv;
        }
    }
}

// ---------------------------------------------------------------------------
extern "C" void kernel_launch(void* const* d_in, const int* in_sizes, int n_in,
                              void* d_out, int out_size) {
    const float* supports = (const float*)d_in[0];  // [2,512,512]
    const float* u        = (const float*)d_in[1];  // [2,512,64]
    const float* s        = (const float*)d_in[2];  // [2,64]
    const float* v        = (const float*)d_in[3];  // [2,512,64]
    const float* bias     = (const float*)d_in[4];  // [2,64]
    const float* inputs   = (const float*)d_in[5];  // [64,12,512,2]
    float* out = (float*)d_out;                     // [2,64,512,512]

    static int smem_set = 0;
    if (!smem_set) {
        cudaFuncSetAttribute(main_kernel,
                             cudaFuncAttributeMaxDynamicSharedMemorySize, SMEM_MAIN);
        smem_set = 1;
    }

    prep_kernel<<<dim3(8, 8, 3), 256>>>(supports, u, s, v, bias, inputs);
    main_kernel<<<dim3(NN / RN, Bn / BG), 256, SMEM_MAIN>>>(out);
}

// round 4
// speedup vs baseline: 1.6587x; 1.1026x over previous
#include <cuda_runtime.h>
#include <math.h>

#define En 2
#define NN 512
#define Bn 64
#define Tt 12
#define Kk 64
#define RN 8     // rows per block tile in main kernel
#define BG 4     // batches per block in main kernel
#define ESTR (Bn * NN * NN)   // e-stride in output

// Dynamic smem layout for main kernel
#define OFF_SUP  0              // float [2][RN][512]  = 32768 B
#define OFF_VSM  32768          // float [2][RN][512]  = 32768 B
#define OFF_XD   65536          // ull   [RN*12]       = 768 B
#define OFF_INV  66304          // float [16]
#define SMEM_MAIN 66560

// Scratch (static device arrays: allocation-free)
__device__ __align__(16) float g_sup[En * NN * NN];      // relu(supports + adaptive)  (2 MB)
__device__ __align__(16) float g_nodesT[Bn * NN * Tt];   // normalized nodes, [b][n][t] (1.5 MB)
__device__ __align__(16) float g_nodesN[Bn * Tt * NN];   // normalized nodes, [b][t][n] (1.5 MB)

// ---------------- packed f32x2 + MUFU helpers ----------------
__device__ __forceinline__ unsigned long long pack2(float a, float b) {
    unsigned long long r;
    asm("mov.b64 %0, {%1, %2};" : "=l"(r) : "f"(a), "f"(b));
    return r;
}
__device__ __forceinline__ void unpack2(unsigned long long p, float& a, float& b) {
    asm("mov.b64 {%0, %1}, %2;" : "=f"(a), "=f"(b) : "l"(p));
}
__device__ __forceinline__ unsigned long long fma2_(unsigned long long a, unsigned long long b, unsigned long long c) {
    unsigned long long d;
    asm("fma.rn.f32x2 %0, %1, %2, %3;" : "=l"(d) : "l"(a), "l"(b), "l"(c));
    return d;
}
__device__ __forceinline__ unsigned long long mul2_(unsigned long long a, unsigned long long b) {
    unsigned long long d;
    asm("mul.rn.f32x2 %0, %1, %2;" : "=l"(d) : "l"(a), "l"(b));
    return d;
}
__device__ __forceinline__ unsigned long long add2_(unsigned long long a, unsigned long long b) {
    unsigned long long d;
    asm("add.rn.f32x2 %0, %1, %2;" : "=l"(d) : "l"(a), "l"(b));
    return d;
}
__device__ __forceinline__ float sqrt_ap(float x) { float r; asm("sqrt.approx.f32 %0, %1;" : "=f"(r) : "f"(x)); return r; }
__device__ __forceinline__ float ex2_neg(float x) { float r; asm("ex2.approx.f32 %0, %1;"  : "=f"(r) : "f"(-x)); return r; }
__device__ __forceinline__ float rcp_ap(float x)  { float r; asm("rcp.approx.f32 %0, %1;"  : "=f"(r) : "f"(x)); return r; }

// ---------------------------------------------------------------------------
// Kernel A (fused prep):
//   z = 0,1 : g_sup[e] = relu(supports + u * diag(s*softplus(bias)) * v^T)
//             64x64 tile, 256 threads, 4x4 micro-tile, TRANSPOSED [k][row] smem
//   z = 2   : L2-normalize node histories -> g_nodesT [b][n][t] + g_nodesN [b][t][n]
// ---------------------------------------------------------------------------
__global__ void __launch_bounds__(256) prep_kernel(const float* __restrict__ supports,
                                                   const float* __restrict__ u,
                                                   const float* __restrict__ s,
                                                   const float* __restrict__ v,
                                                   const float* __restrict__ bias,
                                                   const float* __restrict__ inputs) {
    const int tid = threadIdx.x;

    if (blockIdx.z == 2) {
        // ---- nodes path: 64 blocks x 256 threads, 2 items each ----
        const int g = (blockIdx.y * 8 + blockIdx.x) * 256 + tid;
        #pragma unroll
        for (int it = 0; it < 2; it++) {
            const int i = g + it * 16384;      // b*512 + n
            const int b = i >> 9, n = i & (NN - 1);
            float x[Tt];
            float ss = 0.f;
            #pragma unroll
            for (int t = 0; t < Tt; t++) {
                x[t] = inputs[(((b * Tt + t) * NN) + n) * 2];
                ss = fmaf(x[t], x[t], ss);
            }
            float inv = 1.0f / fmaxf(sqrtf(ss), 1e-12f);
            #pragma unroll
            for (int t = 0; t < Tt; t++) x[t] *= inv;
            // [b][n][t] layout
            float* dst = g_nodesT + (b * NN + n) * Tt;
            *(float4*)(dst)     = make_float4(x[0], x[1], x[2],  x[3]);
            *(float4*)(dst + 4) = make_float4(x[4], x[5], x[6],  x[7]);
            *(float4*)(dst + 8) = make_float4(x[8], x[9], x[10], x[11]);
            // [b][t][n] layout (coalesced per t)
            #pragma unroll
            for (int t = 0; t < Tt; t++)
                g_nodesN[(b * Tt + t) * NN + n] = x[t];
        }
        return;
    }

    // ---- sup path ----
    __shared__ float su_t[Kk][68];   // [k][n], scaled by s*softplus(bias)
    __shared__ float sv_t[Kk][68];   // [k][m]
    __shared__ float ssc[Kk];

    const int e  = blockIdx.z;
    const int n0 = blockIdx.y * 64;
    const int m0 = blockIdx.x * 64;

    if (tid < 64) {
        float bx = bias[e * Kk + tid];
        float sp = (bx > 20.f) ? bx : log1pf(__expf(bx));   // softplus
        ssc[tid] = s[e * Kk + tid] * sp;
    }
    __syncthreads();

    #pragma unroll
    for (int j = 0; j < 4; j++) {
        int idx = tid + j * 256;
        int row = idx & 63;
        int kq  = idx >> 6;        // 0..15
        float4 uv = *(const float4*)(u + (e * NN + n0 + row) * Kk + kq * 4);
        float4 vv = *(const float4*)(v + (e * NN + m0 + row) * Kk + kq * 4);
        su_t[kq * 4 + 0][row] = uv.x * ssc[kq * 4 + 0];
        su_t[kq * 4 + 1][row] = uv.y * ssc[kq * 4 + 1];
        su_t[kq * 4 + 2][row] = uv.z * ssc[kq * 4 + 2];
        su_t[kq * 4 + 3][row] = uv.w * ssc[kq * 4 + 3];
        sv_t[kq * 4 + 0][row] = vv.x;
        sv_t[kq * 4 + 1][row] = vv.y;
        sv_t[kq * 4 + 2][row] = vv.z;
        sv_t[kq * 4 + 3][row] = vv.w;
    }
    __syncthreads();

    const int ry = (tid >> 4) << 2;
    const int rx = (tid & 15) << 2;
    float acc[4][4] = {};

    #pragma unroll
    for (int k = 0; k < 64; k++) {
        float4 a  = *(const float4*)&su_t[k][ry];
        float4 bq = *(const float4*)&sv_t[k][rx];
        acc[0][0] = fmaf(a.x, bq.x, acc[0][0]); acc[0][1] = fmaf(a.x, bq.y, acc[0][1]);
        acc[0][2] = fmaf(a.x, bq.z, acc[0][2]); acc[0][3] = fmaf(a.x, bq.w, acc[0][3]);
        acc[1][0] = fmaf(a.y, bq.x, acc[1][0]); acc[1][1] = fmaf(a.y, bq.y, acc[1][1]);
        acc[1][2] = fmaf(a.y, bq.z, acc[1][2]); acc[1][3] = fmaf(a.y, bq.w, acc[1][3]);
        acc[2][0] = fmaf(a.z, bq.x, acc[2][0]); acc[2][1] = fmaf(a.z, bq.y, acc[2][1]);
        acc[2][2] = fmaf(a.z, bq.z, acc[2][2]); acc[2][3] = fmaf(a.z, bq.w, acc[2][3]);
        acc[3][0] = fmaf(a.w, bq.x, acc[3][0]); acc[3][1] = fmaf(a.w, bq.y, acc[3][1]);
        acc[3][2] = fmaf(a.w, bq.z, acc[3][2]); acc[3][3] = fmaf(a.w, bq.w, acc[3][3]);
    }

    #pragma unroll
    for (int i = 0; i < 4; i++) {
        int base = (e * NN + n0 + ry + i) * NN + m0 + rx;
        float4 sp = *(const float4*)(supports + base);
        float4 o;
        o.x = fmaxf(sp.x + acc[i][0], 0.f);
        o.y = fmaxf(sp.y + acc[i][1], 0.f);
        o.z = fmaxf(sp.z + acc[i][2], 0.f);
        o.w = fmaxf(sp.w + acc[i][3], 0.f);
        *(float4*)(g_sup + base) = o;
    }
}

// ---------------------------------------------------------------------------
// Kernel C: fused main pass.
// 256 threads, each owns an m-pair (packed f32x2), RN rows x BG batches.
// sup tile cached in smem for the whole batch group.
// xm pairs loaded as LDG.64 from [b][t][n] layout (coalesced, pre-packed).
// ---------------------------------------------------------------------------
__global__ void __launch_bounds__(256, 3)
main_kernel(float* __restrict__ out) {
    extern __shared__ char dynsm[];
    float* sup_s = (float*)(dynsm + OFF_SUP);                 // [e*8+r][512]
    float* vsm   = (float*)(dynsm + OFF_VSM);                 // [e*8+r][512]
    unsigned long long* xd = (unsigned long long*)(dynsm + OFF_XD);
    float* invs  = (float*)(dynsm + OFF_INV);

    const int tid  = threadIdx.x;
    const int lane = tid & 31;
    const int warp = tid >> 5;
    const int n0 = blockIdx.x * RN;
    const int b0 = blockIdx.y * BG;
    const int m0 = tid * 2;

    // Stage sup tile (both e): 2048 float4
    #pragma unroll
    for (int i = 0; i < 8; i++) {
        int idx = i * 256 + tid;                    // e*1024 + r*128 + q
        int e = idx >> 10, r = (idx >> 7) & 7, q = idx & 127;
        ((float4*)sup_s)[idx] =
            *(const float4*)(g_sup + e * (NN * NN) + (n0 + r) * NN + q * 4);
    }

    // Precompute batch-invariant writeout pointers + scale indices
    float* outp[8];
    int    ivx[8];
    #pragma unroll
    for (int i = 0; i < 8; i++) {
        int idx = i * 256 + tid;
        int e = idx >> 10, r = (idx >> 7) & 7, q = idx & 127;
        outp[i] = out + e * ESTR + (b0 * NN + n0 + r) * NN + q * 4;
        ivx[i]  = r * 2 + e;
    }

    // 2 * (ln2^-1)^2
    const float C = 4.1627379620112154f;
    const unsigned long long CM = pack2(-C, -C);
    const unsigned long long CP = pack2( C,  C);

    for (int bi = 0; bi < BG; ++bi) {
        const int b = b0 + bi;
        if (bi) __syncthreads();   // prev writeout done before vsm/xd reuse

        // duplicated row-node table (96 values)
        if (tid < RN * Tt) {
            int r = tid / Tt, t = tid - r * Tt;
            float xv = g_nodesT[b * (NN * Tt) + (n0 + r) * Tt + t];
            xd[tid] = pack2(xv, xv);
        }

        // xm pair: 12 coalesced LDG.64, already packed {x[t][m0], x[t][m0+1]}
        unsigned long long xm2[Tt];
        {
            const unsigned long long* xb =
                (const unsigned long long*)(g_nodesN + b * (Tt * NN)) + tid;
            #pragma unroll
            for (int t = 0; t < Tt; t++)
                xm2[t] = xb[t * (NN / 2)];
        }
        __syncthreads();   // xd ready (and, on bi==0, sup_s ready)

        #pragma unroll
        for (int r = 0; r < RN; r++) {
            const ulonglong2* xdp = (const ulonglong2*)&xd[r * Tt];
            ulonglong2 q0 = xdp[0], q1 = xdp[1], q2 = xdp[2];
            ulonglong2 q3 = xdp[3], q4 = xdp[4], q5 = xdp[5];
            unsigned long long pa = mul2_(xm2[0], q0.x);
            unsigned long long pb = mul2_(xm2[1], q0.y);
            pa = fma2_(xm2[2],  q1.x, pa);  pb = fma2_(xm2[3],  q1.y, pb);
            pa = fma2_(xm2[4],  q2.x, pa);  pb = fma2_(xm2[5],  q2.y, pb);
            pa = fma2_(xm2[6],  q3.x, pa);  pb = fma2_(xm2[7],  q3.y, pb);
            pa = fma2_(xm2[8],  q4.x, pa);  pb = fma2_(xm2[9],  q4.y, pb);
            pa = fma2_(xm2[10], q5.x, pa);  pb = fma2_(xm2[11], q5.y, pb);
            unsigned long long inner2 = add2_(pa, pb);
            unsigned long long d2p = fma2_(inner2, CM, CP);  // (1.4427*d)^2 packed
            float d20, d21;
            unpack2(d2p, d20, d21);
            d20 = fmaxf(d20, 0.f);
            d21 = fmaxf(d21, 0.f);
            float f0 = ex2_neg(sqrt_ap(d20)) + 1.0f;
            float f1 = ex2_neg(sqrt_ap(d21)) + 1.0f;

            float2 s0 = *(const float2*)&sup_s[r * NN + m0];
            float2 s1 = *(const float2*)&sup_s[(RN + r) * NN + m0];
            *(float2*)&vsm[r * NN + m0]        = make_float2(f0 * s0.x, f1 * s0.y);
            *(float2*)&vsm[(RN + r) * NN + m0] = make_float2(f0 * s1.x, f1 * s1.y);
        }
        __syncthreads();

        // One warp per row-pair: strided float4 reads + butterfly
        {
            const int r = warp;
            float sum0 = 0.f, sum1 = 0.f;
            const float4* p0 = (const float4*)&vsm[r * NN];
            const float4* p1 = (const float4*)&vsm[(RN + r) * NN];
            #pragma unroll
            for (int i = 0; i < 4; i++) {
                float4 v0 = p0[lane + 32 * i];
                float4 v1 = p1[lane + 32 * i];
                sum0 += (v0.x + v0.y) + (v0.z + v0.w);
                sum1 += (v1.x + v1.y) + (v1.z + v1.w);
            }
            #pragma unroll
            for (int o = 16; o > 0; o >>= 1) {
                sum0 += __shfl_xor_sync(0xffffffffu, sum0, o);
                sum1 += __shfl_xor_sync(0xffffffffu, sum1, o);
            }
            if (lane == 0) {
                invs[r * 2]     = rcp_ap(fmaxf(sum0, 1e-12f));
                invs[r * 2 + 1] = rcp_ap(fmaxf(sum1, 1e-12f));
            }
        }
        __syncthreads();

        // Scaled write-out, float4 coalesced (batch-invariant pointers + bi offset)
        const int bo = bi * (NN * NN);
        #pragma unroll
        for (int i = 0; i < 8; i++) {
            float iv = invs[ivx[i]];
            float4 vv = ((const float4*)vsm)[i * 256 + tid];
            vv.x *= iv; vv.y *= iv; vv.z *= iv; vv.w *= iv;
            *(float4*)(outp[i] + bo) = vv;
        }
    }
}

// ---------------------------------------------------------------------------
extern "C" void kernel_launch(void* const* d_in, const int* in_sizes, int n_in,
                              void* d_out, int out_size) {
    const float* supports = (const float*)d_in[0];  // [2,512,512]
    const float* u        = (const float*)d_in[1];  // [2,512,64]
    const float* s        = (const float*)d_in[2];  // [2,64]
    const float* v        = (const float*)d_in[3];  // [2,512,64]
    const float* bias     = (const float*)d_in[4];  // [2,64]
    const float* inputs   = (const float*)d_in[5];  // [64,12,512,2]
    float* out = (float*)d_out;                     // [2,64,512,512]

    static int smem_set = 0;
    if (!smem_set) {
        cudaFuncSetAttribute(main_kernel,
                             cudaFuncAttributeMaxDynamicSharedMemorySize, SMEM_MAIN);
        smem_set = 1;
    }

    prep_kernel<<<dim3(8, 8, 3), 256>>>(supports, u, s, v, bias, inputs);
    main_kernel<<<dim3(NN / RN, Bn / BG), 256, SMEM_MAIN>>>(out);
}

// round 5
// speedup vs baseline: 1.7927x; 1.0808x over previous
#include <cuda_runtime.h>
#include <math.h>

#define En 2
#define NN 512
#define Bn 64
#define Tt 12
#define Kk 64
#define RN 8     // rows per block tile in main kernel
#define BG 4     // batches per block in main kernel
#define ESTR (Bn * NN * NN)   // e-stride in output

// Scratch (static device arrays: allocation-free)
__device__ __align__(16) float g_sup[En * NN * NN];      // relu(supports + adaptive)  (2 MB)
__device__ __align__(16) float g_nodesT[Bn * NN * Tt];   // normalized nodes, [b][n][t] (1.5 MB)
__device__ __align__(16) float g_nodesN[Bn * Tt * NN];   // normalized nodes, [b][t][n] (1.5 MB)

// ---------------- packed f32x2 + MUFU helpers ----------------
__device__ __forceinline__ unsigned long long pack2(float a, float b) {
    unsigned long long r;
    asm("mov.b64 %0, {%1, %2};" : "=l"(r) : "f"(a), "f"(b));
    return r;
}
__device__ __forceinline__ void unpack2(unsigned long long p, float& a, float& b) {
    asm("mov.b64 {%0, %1}, %2;" : "=f"(a), "=f"(b) : "l"(p));
}
__device__ __forceinline__ unsigned long long fma2_(unsigned long long a, unsigned long long b, unsigned long long c) {
    unsigned long long d;
    asm("fma.rn.f32x2 %0, %1, %2, %3;" : "=l"(d) : "l"(a), "l"(b), "l"(c));
    return d;
}
__device__ __forceinline__ unsigned long long mul2_(unsigned long long a, unsigned long long b) {
    unsigned long long d;
    asm("mul.rn.f32x2 %0, %1, %2;" : "=l"(d) : "l"(a), "l"(b));
    return d;
}
__device__ __forceinline__ unsigned long long add2_(unsigned long long a, unsigned long long b) {
    unsigned long long d;
    asm("add.rn.f32x2 %0, %1, %2;" : "=l"(d) : "l"(a), "l"(b));
    return d;
}
__device__ __forceinline__ float sqrt_ap(float x) { float r; asm("sqrt.approx.f32 %0, %1;" : "=f"(r) : "f"(x)); return r; }
__device__ __forceinline__ float ex2_neg(float x) { float r; asm("ex2.approx.f32 %0, %1;"  : "=f"(r) : "f"(-x)); return r; }
__device__ __forceinline__ float rcp_ap(float x)  { float r; asm("rcp.approx.f32 %0, %1;"  : "=f"(r) : "f"(x)); return r; }
__device__ __forceinline__ float hadd2(unsigned long long p) {
    float a, b; unpack2(p, a, b); return a + b;
}

// ---------------------------------------------------------------------------
// Kernel A (fused prep):
//   z = 0,1 : g_sup[e] = relu(supports + u * diag(s*softplus(bias)) * v^T)
//   z = 2   : L2-normalize node histories -> g_nodesT [b][n][t] + g_nodesN [b][t][n]
// ---------------------------------------------------------------------------
__global__ void __launch_bounds__(256) prep_kernel(const float* __restrict__ supports,
                                                   const float* __restrict__ u,
                                                   const float* __restrict__ s,
                                                   const float* __restrict__ v,
                                                   const float* __restrict__ bias,
                                                   const float* __restrict__ inputs) {
    const int tid = threadIdx.x;

    if (blockIdx.z == 2) {
        const int g = (blockIdx.y * 8 + blockIdx.x) * 256 + tid;
        #pragma unroll
        for (int it = 0; it < 2; it++) {
            const int i = g + it * 16384;      // b*512 + n
            const int b = i >> 9, n = i & (NN - 1);
            float x[Tt];
            float ss = 0.f;
            #pragma unroll
            for (int t = 0; t < Tt; t++) {
                x[t] = inputs[(((b * Tt + t) * NN) + n) * 2];
                ss = fmaf(x[t], x[t], ss);
            }
            float inv = 1.0f / fmaxf(sqrtf(ss), 1e-12f);
            #pragma unroll
            for (int t = 0; t < Tt; t++) x[t] *= inv;
            float* dst = g_nodesT + (b * NN + n) * Tt;
            *(float4*)(dst)     = make_float4(x[0], x[1], x[2],  x[3]);
            *(float4*)(dst + 4) = make_float4(x[4], x[5], x[6],  x[7]);
            *(float4*)(dst + 8) = make_float4(x[8], x[9], x[10], x[11]);
            #pragma unroll
            for (int t = 0; t < Tt; t++)
                g_nodesN[(b * Tt + t) * NN + n] = x[t];
        }
        return;
    }

    __shared__ float su_t[Kk][68];
    __shared__ float sv_t[Kk][68];
    __shared__ float ssc[Kk];

    const int e  = blockIdx.z;
    const int n0 = blockIdx.y * 64;
    const int m0 = blockIdx.x * 64;

    if (tid < 64) {
        float bx = bias[e * Kk + tid];
        float sp = (bx > 20.f) ? bx : log1pf(__expf(bx));   // softplus
        ssc[tid] = s[e * Kk + tid] * sp;
    }
    __syncthreads();

    #pragma unroll
    for (int j = 0; j < 4; j++) {
        int idx = tid + j * 256;
        int row = idx & 63;
        int kq  = idx >> 6;
        float4 uv = *(const float4*)(u + (e * NN + n0 + row) * Kk + kq * 4);
        float4 vv = *(const float4*)(v + (e * NN + m0 + row) * Kk + kq * 4);
        su_t[kq * 4 + 0][row] = uv.x * ssc[kq * 4 + 0];
        su_t[kq * 4 + 1][row] = uv.y * ssc[kq * 4 + 1];
        su_t[kq * 4 + 2][row] = uv.z * ssc[kq * 4 + 2];
        su_t[kq * 4 + 3][row] = uv.w * ssc[kq * 4 + 3];
        sv_t[kq * 4 + 0][row] = vv.x;
        sv_t[kq * 4 + 1][row] = vv.y;
        sv_t[kq * 4 + 2][row] = vv.z;
        sv_t[kq * 4 + 3][row] = vv.w;
    }
    __syncthreads();

    const int ry = (tid >> 4) << 2;
    const int rx = (tid & 15) << 2;
    float acc[4][4] = {};

    #pragma unroll
    for (int k = 0; k < 64; k++) {
        float4 a  = *(const float4*)&su_t[k][ry];
        float4 bq = *(const float4*)&sv_t[k][rx];
        acc[0][0] = fmaf(a.x, bq.x, acc[0][0]); acc[0][1] = fmaf(a.x, bq.y, acc[0][1]);
        acc[0][2] = fmaf(a.x, bq.z, acc[0][2]); acc[0][3] = fmaf(a.x, bq.w, acc[0][3]);
        acc[1][0] = fmaf(a.y, bq.x, acc[1][0]); acc[1][1] = fmaf(a.y, bq.y, acc[1][1]);
        acc[1][2] = fmaf(a.y, bq.z, acc[1][2]); acc[1][3] = fmaf(a.y, bq.w, acc[1][3]);
        acc[2][0] = fmaf(a.z, bq.x, acc[2][0]); acc[2][1] = fmaf(a.z, bq.y, acc[2][1]);
        acc[2][2] = fmaf(a.z, bq.z, acc[2][2]); acc[2][3] = fmaf(a.z, bq.w, acc[2][3]);
        acc[3][0] = fmaf(a.w, bq.x, acc[3][0]); acc[3][1] = fmaf(a.w, bq.y, acc[3][1]);
        acc[3][2] = fmaf(a.w, bq.z, acc[3][2]); acc[3][3] = fmaf(a.w, bq.w, acc[3][3]);
    }

    #pragma unroll
    for (int i = 0; i < 4; i++) {
        int base = (e * NN + n0 + ry + i) * NN + m0 + rx;
        float4 sp = *(const float4*)(supports + base);
        float4 o;
        o.x = fmaxf(sp.x + acc[i][0], 0.f);
        o.y = fmaxf(sp.y + acc[i][1], 0.f);
        o.z = fmaxf(sp.z + acc[i][2], 0.f);
        o.w = fmaxf(sp.w + acc[i][3], 0.f);
        *(float4*)(g_sup + base) = o;
    }
}

// ---------------------------------------------------------------------------
// Kernel C: fused main pass, register-resident sup & val.
// 256 threads, each owns an m-pair. Only row-sum partials + xd go through smem.
// ---------------------------------------------------------------------------
__global__ void __launch_bounds__(256, 2)
main_kernel(float* __restrict__ out) {
    __shared__ float ps[2 * RN][256];                 // row-sum partials, 16 KB
    __shared__ unsigned long long xd[RN * Tt];        // packed {xn,xn} per tile row
    __shared__ float invs[2 * RN];

    const int tid  = threadIdx.x;
    const int lane = tid & 31;
    const int warp = tid >> 5;
    const int n0 = blockIdx.x * RN;
    const int b0 = blockIdx.y * BG;
    const int m0 = tid * 2;

    // sup (relu'd) in registers: batch-invariant, this thread's m-pair only
    unsigned long long sup0[RN], sup1[RN];
    #pragma unroll
    for (int r = 0; r < RN; r++) {
        sup0[r] = *(const unsigned long long*)(g_sup + (n0 + r) * NN + m0);
        sup1[r] = *(const unsigned long long*)(g_sup + NN * NN + (n0 + r) * NN + m0);
    }

    // 2 * (ln2^-1)^2
    const float C = 4.1627379620112154f;
    const unsigned long long CM = pack2(-C, -C);
    const unsigned long long CP = pack2( C,  C);

    for (int bi = 0; bi < BG; ++bi) {
        const int b = b0 + bi;

        // duplicated row-node table (96 values)
        if (tid < RN * Tt) {
            int r = tid / Tt, t = tid - r * Tt;
            float xv = g_nodesT[b * (NN * Tt) + (n0 + r) * Tt + t];
            xd[tid] = pack2(xv, xv);
        }

        // xm pair: 12 coalesced LDG.64, already packed {x[t][m0], x[t][m0+1]}
        unsigned long long xm2[Tt];
        {
            const unsigned long long* xb =
                (const unsigned long long*)(g_nodesN + b * (Tt * NN)) + tid;
            #pragma unroll
            for (int t = 0; t < Tt; t++)
                xm2[t] = xb[t * (NN / 2)];
        }
        __syncthreads();   // xd ready; also fences prev-batch writeout/reduce

        unsigned long long val0[RN], val1[RN];
        #pragma unroll
        for (int r = 0; r < RN; r++) {
            const ulonglong2* xdp = (const ulonglong2*)&xd[r * Tt];
            ulonglong2 q0 = xdp[0], q1 = xdp[1], q2 = xdp[2];
            ulonglong2 q3 = xdp[3], q4 = xdp[4], q5 = xdp[5];
            unsigned long long pa = mul2_(xm2[0], q0.x);
            unsigned long long pb = mul2_(xm2[1], q0.y);
            pa = fma2_(xm2[2],  q1.x, pa);  pb = fma2_(xm2[3],  q1.y, pb);
            pa = fma2_(xm2[4],  q2.x, pa);  pb = fma2_(xm2[5],  q2.y, pb);
            pa = fma2_(xm2[6],  q3.x, pa);  pb = fma2_(xm2[7],  q3.y, pb);
            pa = fma2_(xm2[8],  q4.x, pa);  pb = fma2_(xm2[9],  q4.y, pb);
            pa = fma2_(xm2[10], q5.x, pa);  pb = fma2_(xm2[11], q5.y, pb);
            unsigned long long inner2 = add2_(pa, pb);
            unsigned long long d2p = fma2_(inner2, CM, CP);  // (1.4427*d)^2 packed
            float d20, d21;
            unpack2(d2p, d20, d21);
            d20 = fmaxf(d20, 0.f);
            d21 = fmaxf(d21, 0.f);
            float f0 = ex2_neg(sqrt_ap(d20)) + 1.0f;
            float f1 = ex2_neg(sqrt_ap(d21)) + 1.0f;
            unsigned long long fp = pack2(f0, f1);

            val0[r] = mul2_(fp, sup0[r]);
            val1[r] = mul2_(fp, sup1[r]);
            ps[r * 2][tid]     = hadd2(val0[r]);
            ps[r * 2 + 1][tid] = hadd2(val1[r]);
        }
        __syncthreads();

        // One warp per row-pair: 2 rows x 256 partials each
        {
            float sum0 = 0.f, sum1 = 0.f;
            const float4* p0 = (const float4*)ps[warp * 2];
            const float4* p1 = (const float4*)ps[warp * 2 + 1];
            #pragma unroll
            for (int i = 0; i < 2; i++) {
                float4 v0 = p0[lane + 32 * i];
                float4 v1 = p1[lane + 32 * i];
                sum0 += (v0.x + v0.y) + (v0.z + v0.w);
                sum1 += (v1.x + v1.y) + (v1.z + v1.w);
            }
            #pragma unroll
            for (int o = 16; o > 0; o >>= 1) {
                sum0 += __shfl_xor_sync(0xffffffffu, sum0, o);
                sum1 += __shfl_xor_sync(0xffffffffu, sum1, o);
            }
            if (lane == 0) {
                invs[warp * 2]     = rcp_ap(fmaxf(sum0, 1e-12f));
                invs[warp * 2 + 1] = rcp_ap(fmaxf(sum1, 1e-12f));
            }
        }
        __syncthreads();

        // Direct register -> gmem writeout (STG.64, coalesced)
        float* ob = out + (b * NN + n0) * NN + m0;
        #pragma unroll
        for (int r = 0; r < RN; r++) {
            float iv0 = invs[r * 2], iv1 = invs[r * 2 + 1];
            *(unsigned long long*)(ob + r * NN) =
                mul2_(val0[r], pack2(iv0, iv0));
            *(unsigned long long*)(ob + ESTR + r * NN) =
                mul2_(val1[r], pack2(iv1, iv1));
        }
    }
}

// ---------------------------------------------------------------------------
extern "C" void kernel_launch(void* const* d_in, const int* in_sizes, int n_in,
                              void* d_out, int out_size) {
    const float* supports = (const float*)d_in[0];  // [2,512,512]
    const float* u        = (const float*)d_in[1];  // [2,512,64]
    const float* s        = (const float*)d_in[2];  // [2,64]
    const float* v        = (const float*)d_in[3];  // [2,512,64]
    const float* bias     = (const float*)d_in[4];  // [2,64]
    const float* inputs   = (const float*)d_in[5];  // [64,12,512,2]
    float* out = (float*)d_out;                     // [2,64,512,512]

    prep_kernel<<<dim3(8, 8, 3), 256>>>(supports, u, s, v, bias, inputs);
    main_kernel<<<dim3(NN / RN, Bn / BG), 256>>>(out);
}